// round 2
// baseline (speedup 1.0000x reference)
#include <cuda_runtime.h>

#define Bb     2
#define Ss     1024
#define Dd     1024
#define Hh     16
#define HDh    64
#define NT     (Bb*Ss)       // 2048 tokens
#define Ee     31
#define INTERi 1024
#define EPSf   1e-5f
#define SLOTS  (NT*3)        // 6144 (token, rank) pairs

// ---------------- scratch (device globals; no allocation) ----------------
__device__ float g_xn  [NT*Dd];
__device__ float g_qb  [NT*Dd];     // [B,H,S,HD]
__device__ float g_kb  [NT*Dd];
__device__ float g_vb  [NT*Dd];
__device__ float g_ctx [NT*Dd];     // [B,S,H*HD]
__device__ float g_attn[NT*Dd];
__device__ float g_an  [NT*Dd];
__device__ float g_t1  [NT*INTERi];
__device__ float g_h   [SLOTS*INTERi];   // compacted expert hidden
__device__ float g_part[SLOTS*Dd];       // per-(token,rank) routed partials
__device__ int   g_topi[SLOTS];
__device__ float g_topv[SLOTS];
__device__ int   g_cnt[Ee];
__device__ int   g_off[Ee];
__device__ int   g_cur[Ee];
__device__ int   g_slot_tok [SLOTS];
__device__ int   g_slot_rank[SLOTS];
__device__ float g_slot_gate[SLOTS];

__device__ __forceinline__ float gelu_f(float v) {
    return 0.5f * v * (1.0f + erff(v * 0.70710678118654752f));
}

// ---------------- reset (graph-replay safe) ----------------
__global__ void reset_kernel() {
    int t = threadIdx.x;
    if (t < Ee) { g_cnt[t] = 0; g_cur[t] = 0; }
}

// ---------------- RMSNorm ----------------
__global__ void rmsnorm_kernel(const float* __restrict__ in,
                               const float* __restrict__ gamma,
                               float* __restrict__ out) {
    int row = blockIdx.x;
    const float* p = in + row * Dd;
    float ss = 0.f;
    for (int d = threadIdx.x; d < Dd; d += blockDim.x) { float v = p[d]; ss += v * v; }
    for (int o = 16; o; o >>= 1) ss += __shfl_xor_sync(0xffffffffu, ss, o);
    __shared__ float red[8];
    int w = threadIdx.x >> 5;
    if ((threadIdx.x & 31) == 0) red[w] = ss;
    __syncthreads();
    if (threadIdx.x < 8) {
        float v = red[threadIdx.x];
        for (int o = 4; o; o >>= 1) v += __shfl_xor_sync(0xffu, v, o);
        if (threadIdx.x == 0) red[0] = v;
    }
    __syncthreads();
    float rinv = rsqrtf(red[0] * (1.0f / Dd) + EPSf);
    for (int d = threadIdx.x; d < Dd; d += blockDim.x)
        out[row * Dd + d] = p[d] * rinv * gamma[d];
}

// ---------------- generic tiled GEMM: C = A[MxK] @ B[KxN] + bias ----------------
// mode 0: plain   1: gelu   2: + res1 (+ res2 if non-null)   3: scatter to [B,H,S,HD]
__global__ void gemm_kernel(const float* __restrict__ A, const float* __restrict__ Bm,
                            const float* __restrict__ bias, float* __restrict__ C,
                            int M, int N, int K, int mode,
                            const float* __restrict__ res1, const float* __restrict__ res2) {
    __shared__ __align__(16) float As[16][64];
    __shared__ __align__(16) float Bs[16][64];
    int tid = threadIdx.x, tx = tid & 15, ty = tid >> 4;
    int nb = blockIdx.x * 64, mb = blockIdx.y * 64;
    float acc[4][4] = {};
    for (int k0 = 0; k0 < K; k0 += 16) {
        for (int i = tid; i < 1024; i += 256) {
            int kk = i >> 6, m = i & 63;
            As[kk][m] = A[(mb + m) * K + k0 + kk];
        }
        for (int i = tid; i < 1024; i += 256) {
            int kk = i >> 6, n = i & 63;
            Bs[kk][n] = Bm[(k0 + kk) * N + nb + n];
        }
        __syncthreads();
#pragma unroll
        for (int kk = 0; kk < 16; kk++) {
            float4 a = *(const float4*)&As[kk][ty * 4];
            float4 b = *(const float4*)&Bs[kk][tx * 4];
            float av[4] = {a.x, a.y, a.z, a.w};
            float bv[4] = {b.x, b.y, b.z, b.w};
#pragma unroll
            for (int i = 0; i < 4; i++)
#pragma unroll
                for (int j = 0; j < 4; j++) acc[i][j] += av[i] * bv[j];
        }
        __syncthreads();
    }
#pragma unroll
    for (int i = 0; i < 4; i++) {
        int m = mb + ty * 4 + i;
        if (m >= M) continue;
#pragma unroll
        for (int j = 0; j < 4; j++) {
            int n = nb + tx * 4 + j;
            float v = acc[i][j] + bias[n];
            if (mode == 1) v = gelu_f(v);
            else if (mode == 2) {
                v += res1[m * N + n];
                if (res2) v += res2[m * N + n];
            }
            if (mode == 3) {
                int b = m >> 10, s = m & 1023, h = n >> 6, hd = n & 63;
                C[(((b * Hh + h) * Ss + s) << 6) + hd] = v;
            } else C[m * N + n] = v;
        }
    }
}

// ---------------- RoPE in place on [B,H,S,HD] ----------------
__global__ void rope_kernel(float* __restrict__ p, const float* __restrict__ theta) {
    int v = blockIdx.x;                 // 0..B*H*S-1
    int s = v & (Ss - 1);
    float* base = p + v * HDh;
    int i = threadIdx.x;                // 0..31
    float x1 = base[2 * i], x2 = base[2 * i + 1];
    float ang = (float)s * theta[i];
    float c = cosf(ang), sn = sinf(ang);
    __syncwarp();
    base[i]      = x1 * c - x2 * sn;
    base[32 + i] = x1 * sn + x2 * c;
}

// ---------------- causal flash attention ----------------
// grid (S/128, B*H), 128 threads; thread owns 1 query.
__global__ void attn_kernel(const float* __restrict__ Q, const float* __restrict__ Kt,
                            const float* __restrict__ V, float* __restrict__ ctx) {
    int bh = blockIdx.y;
    int b = bh / Hh, h = bh % Hh;
    int qbase = blockIdx.x * 128;
    int t = threadIdx.x;
    int q = qbase + t;
    const float4* qrow = (const float4*)(Q + (bh * Ss + q) * HDh);
    float4 qr[16];
#pragma unroll
    for (int i = 0; i < 16; i++) qr[i] = qrow[i];
    float4 o[16];
#pragma unroll
    for (int i = 0; i < 16; i++) o[i] = make_float4(0.f, 0.f, 0.f, 0.f);
    float m = -1e30f, l = 0.f;
    __shared__ __align__(16) float4 ks[1024];
    __shared__ __align__(16) float4 vs[1024];
    int ntiles = qbase / 64 + 2;
    const float scale = 0.125f;
    for (int tile = 0; tile < ntiles; tile++) {
        int kb = tile * 64;
        const float4* kp = (const float4*)(Kt + (bh * Ss + kb) * HDh);
        const float4* vp = (const float4*)(V  + (bh * Ss + kb) * HDh);
        __syncthreads();
        for (int i = t; i < 1024; i += 128) { ks[i] = kp[i]; vs[i] = vp[i]; }
        __syncthreads();
        int jmax = q - kb + 1;
        if (jmax > 64) jmax = 64;
        for (int j = 0; j < jmax; j++) {
            float s_ = 0.f;
#pragma unroll
            for (int i = 0; i < 16; i++) {
                float4 kv = ks[j * 16 + i];
                s_ += qr[i].x * kv.x + qr[i].y * kv.y + qr[i].z * kv.z + qr[i].w * kv.w;
            }
            s_ *= scale;
            if (s_ <= m) {
                float p = __expf(s_ - m);
                l += p;
#pragma unroll
                for (int i = 0; i < 16; i++) {
                    float4 vv = vs[j * 16 + i];
                    o[i].x += p * vv.x; o[i].y += p * vv.y;
                    o[i].z += p * vv.z; o[i].w += p * vv.w;
                }
            } else {
                float corr = __expf(m - s_);
                m = s_;
                l = l * corr + 1.f;
#pragma unroll
                for (int i = 0; i < 16; i++) {
                    float4 vv = vs[j * 16 + i];
                    o[i].x = o[i].x * corr + vv.x; o[i].y = o[i].y * corr + vv.y;
                    o[i].z = o[i].z * corr + vv.z; o[i].w = o[i].w * corr + vv.w;
                }
            }
        }
    }
    float rl = 1.f / l;
    float4* out = (float4*)(ctx + (b * Ss + q) * Dd + h * HDh);
#pragma unroll
    for (int i = 0; i < 16; i++)
        out[i] = make_float4(o[i].x * rl, o[i].y * rl, o[i].z * rl, o[i].w * rl);
}

// ---------------- router: logits, softmax(31), top-3, counts ----------------
__global__ void router_kernel(const float* __restrict__ an, const float* __restrict__ W,
                              const float* __restrict__ bias) {
    int tkn = blockIdx.x;
    __shared__ float xs[Dd];
    for (int d = threadIdx.x; d < Dd; d += 32) xs[d] = an[tkn * Dd + d];
    __syncwarp();
    int e = threadIdx.x;
    float logit = -1e30f;
    if (e < Ee) {
        float acc = bias[e];
        for (int d = 0; d < Dd; d++) acc += xs[d] * W[d * Ee + e];
        logit = acc;
    }
    float mx = logit;
    for (int o = 16; o; o >>= 1) mx = fmaxf(mx, __shfl_xor_sync(0xffffffffu, mx, o));
    float ex = (e < Ee) ? __expf(logit - mx) : 0.f;
    float sm = ex;
    for (int o = 16; o; o >>= 1) sm += __shfl_xor_sync(0xffffffffu, sm, o);
    float pw = ex / sm;
    for (int it = 0; it < 3; it++) {
        float bv = pw; int bi = e;
        for (int o = 16; o; o >>= 1) {
            float ov = __shfl_xor_sync(0xffffffffu, bv, o);
            int   oi = __shfl_xor_sync(0xffffffffu, bi, o);
            if (ov > bv || (ov == bv && oi < bi)) { bv = ov; bi = oi; }
        }
        if (threadIdx.x == 0) {
            g_topi[tkn * 3 + it] = bi;
            g_topv[tkn * 3 + it] = bv;
            atomicAdd(&g_cnt[bi], 1);
        }
        if (e == bi) pw = -1.f;
    }
}

__global__ void scan_kernel() {
    if (threadIdx.x == 0) {
        int s = 0;
        for (int e = 0; e < Ee; e++) { g_off[e] = s; s += g_cnt[e]; }
    }
}

__global__ void fill_kernel() {
    int i = blockIdx.x * 256 + threadIdx.x;
    if (i >= SLOTS) return;
    int tkn = i / 3, r = i - tkn * 3;
    int e = g_topi[i];
    int pos = atomicAdd(&g_cur[e], 1);
    int slot = g_off[e] + pos;
    g_slot_tok[slot] = tkn;
    g_slot_rank[slot] = r;
    g_slot_gate[slot] = g_topv[i];
}

// ---------------- expert GEMM 1: h = gelu(gather(an) @ W1[e] + b1[e]) ----------------
// grid (INTER/64, 32, 31), early-exit past cnt
__global__ void egemm1_kernel(const float* __restrict__ re_w1, const float* __restrict__ re_b1) {
    int e = blockIdx.z;
    int cnt = g_cnt[e];
    int mb = blockIdx.y * 64;
    if (mb >= cnt) return;
    int off = g_off[e];
    const float* Bm = re_w1 + e * (Dd * INTERi);
    __shared__ __align__(16) float As[16][64];
    __shared__ __align__(16) float Bs[16][64];
    int tid = threadIdx.x, tx = tid & 15, ty = tid >> 4;
    int nb = blockIdx.x * 64;
    float acc[4][4] = {};
    for (int k0 = 0; k0 < Dd; k0 += 16) {
        for (int i = tid; i < 1024; i += 256) {
            int kk = i >> 6, m = i & 63;
            int row = mb + m;
            float v = 0.f;
            if (row < cnt) v = g_an[g_slot_tok[off + row] * Dd + k0 + kk];
            As[kk][m] = v;
        }
        for (int i = tid; i < 1024; i += 256) {
            int kk = i >> 6, n = i & 63;
            Bs[kk][n] = Bm[(k0 + kk) * INTERi + nb + n];
        }
        __syncthreads();
#pragma unroll
        for (int kk = 0; kk < 16; kk++) {
            float4 a = *(const float4*)&As[kk][ty * 4];
            float4 b = *(const float4*)&Bs[kk][tx * 4];
            float av[4] = {a.x, a.y, a.z, a.w};
            float bv[4] = {b.x, b.y, b.z, b.w};
#pragma unroll
            for (int i = 0; i < 4; i++)
#pragma unroll
                for (int j = 0; j < 4; j++) acc[i][j] += av[i] * bv[j];
        }
        __syncthreads();
    }
#pragma unroll
    for (int i = 0; i < 4; i++) {
        int row = mb + ty * 4 + i;
        if (row >= cnt) continue;
#pragma unroll
        for (int j = 0; j < 4; j++) {
            int n = nb + tx * 4 + j;
            g_h[(off + row) * INTERi + n] = gelu_f(acc[i][j] + re_b1[e * INTERi + n]);
        }
    }
}

// ---------------- expert GEMM 2: part[(tok,rank)] = gate * (h @ W2[e] + b2[e]) ----------------
__global__ void egemm2_kernel(const float* __restrict__ re_w2, const float* __restrict__ re_b2) {
    int e = blockIdx.z;
    int cnt = g_cnt[e];
    int mb = blockIdx.y * 64;
    if (mb >= cnt) return;
    int off = g_off[e];
    const float* Bm = re_w2 + e * (INTERi * Dd);
    __shared__ __align__(16) float As[16][64];
    __shared__ __align__(16) float Bs[16][64];
    int tid = threadIdx.x, tx = tid & 15, ty = tid >> 4;
    int nb = blockIdx.x * 64;
    float acc[4][4] = {};
    for (int k0 = 0; k0 < INTERi; k0 += 16) {
        for (int i = tid; i < 1024; i += 256) {
            int kk = i >> 6, m = i & 63;
            int row = mb + m;
            float v = 0.f;
            if (row < cnt) v = g_h[(off + row) * INTERi + k0 + kk];
            As[kk][m] = v;
        }
        for (int i = tid; i < 1024; i += 256) {
            int kk = i >> 6, n = i & 63;
            Bs[kk][n] = Bm[(k0 + kk) * Dd + nb + n];
        }
        __syncthreads();
#pragma unroll
        for (int kk = 0; kk < 16; kk++) {
            float4 a = *(const float4*)&As[kk][ty * 4];
            float4 b = *(const float4*)&Bs[kk][tx * 4];
            float av[4] = {a.x, a.y, a.z, a.w};
            float bv[4] = {b.x, b.y, b.z, b.w};
#pragma unroll
            for (int i = 0; i < 4; i++)
#pragma unroll
                for (int j = 0; j < 4; j++) acc[i][j] += av[i] * bv[j];
        }
        __syncthreads();
    }
#pragma unroll
    for (int i = 0; i < 4; i++) {
        int row = mb + ty * 4 + i;
        if (row >= cnt) continue;
        int slot = off + row;
        int tok = g_slot_tok[slot];
        int rnk = g_slot_rank[slot];
        float gate = g_slot_gate[slot];
#pragma unroll
        for (int j = 0; j < 4; j++) {
            int n = nb + tx * 4 + j;
            g_part[(tok * 3 + rnk) * Dd + n] = gate * (acc[i][j] + re_b2[e * Dd + n]);
        }
    }
}

// ---------------- final: out += routed partials ----------------
__global__ void final_kernel(float* __restrict__ out) {
    int i = blockIdx.x * 256 + threadIdx.x;   // < NT*Dd
    int t = i >> 10, n = i & 1023;
    float v = out[i];
    v += g_part[(t * 3 + 0) * Dd + n];
    v += g_part[(t * 3 + 1) * Dd + n];
    v += g_part[(t * 3 + 2) * Dd + n];
    out[i] = v;
}

// ---------------- launch ----------------
extern "C" void kernel_launch(void* const* d_in, const int* in_sizes, int n_in,
                              void* d_out, int out_size) {
    const float* x      = (const float*)d_in[0];
    const float* theta  = (const float*)d_in[2];
    const float* gamma1 = (const float*)d_in[3];
    const float* gamma2 = (const float*)d_in[4];
    const float* q_w  = (const float*)d_in[5];  const float* q_b  = (const float*)d_in[6];
    const float* k_w  = (const float*)d_in[7];  const float* k_b  = (const float*)d_in[8];
    const float* v_w  = (const float*)d_in[9];  const float* v_b  = (const float*)d_in[10];
    const float* o_w  = (const float*)d_in[11]; const float* o_b  = (const float*)d_in[12];
    const float* r_w  = (const float*)d_in[13]; const float* r_b  = (const float*)d_in[14];
    const float* sw1  = (const float*)d_in[15]; const float* sb1  = (const float*)d_in[16];
    const float* sw2  = (const float*)d_in[17]; const float* sb2  = (const float*)d_in[18];
    const float* rw1  = (const float*)d_in[19]; const float* rb1  = (const float*)d_in[20];
    const float* rw2  = (const float*)d_in[21]; const float* rb2  = (const float*)d_in[22];
    float* out = (float*)d_out;

    float *xn, *qb, *kb, *vb, *ctx, *attn, *an, *t1;
    cudaGetSymbolAddress((void**)&xn,   g_xn);
    cudaGetSymbolAddress((void**)&qb,   g_qb);
    cudaGetSymbolAddress((void**)&kb,   g_kb);
    cudaGetSymbolAddress((void**)&vb,   g_vb);
    cudaGetSymbolAddress((void**)&ctx,  g_ctx);
    cudaGetSymbolAddress((void**)&attn, g_attn);
    cudaGetSymbolAddress((void**)&an,   g_an);
    cudaGetSymbolAddress((void**)&t1,   g_t1);

    dim3 gThreads(256);
    dim3 gGrid(Dd / 64, NT / 64);          // 16 x 32

    reset_kernel<<<1, 32>>>();
    rmsnorm_kernel<<<NT, 256>>>(x, gamma1, xn);

    gemm_kernel<<<gGrid, gThreads>>>(xn, q_w, q_b, qb, NT, Dd, Dd, 3, nullptr, nullptr);
    gemm_kernel<<<gGrid, gThreads>>>(xn, k_w, k_b, kb, NT, Dd, Dd, 3, nullptr, nullptr);
    gemm_kernel<<<gGrid, gThreads>>>(xn, v_w, v_b, vb, NT, Dd, Dd, 3, nullptr, nullptr);

    rope_kernel<<<Bb * Hh * Ss, 32>>>(qb, theta);
    rope_kernel<<<Bb * Hh * Ss, 32>>>(kb, theta);

    attn_kernel<<<dim3(Ss / 128, Bb * Hh), 128>>>(qb, kb, vb, ctx);

    gemm_kernel<<<gGrid, gThreads>>>(ctx, o_w, o_b, attn, NT, Dd, Dd, 2, xn, nullptr);
    rmsnorm_kernel<<<NT, 256>>>(attn, gamma2, an);

    gemm_kernel<<<dim3(INTERi / 64, NT / 64), gThreads>>>(an, sw1, sb1, t1, NT, INTERi, Dd, 1, nullptr, nullptr);
    gemm_kernel<<<gGrid, gThreads>>>(t1, sw2, sb2, out, NT, Dd, INTERi, 2, an, attn);

    router_kernel<<<NT, 32>>>(an, r_w, r_b);
    scan_kernel<<<1, 32>>>();
    fill_kernel<<<(SLOTS + 255) / 256, 256>>>();

    egemm1_kernel<<<dim3(INTERi / 64, NT / 64, Ee), gThreads>>>(rw1, rb1);
    egemm2_kernel<<<dim3(Dd / 64, NT / 64, Ee), gThreads>>>(rw2, rb2);

    final_kernel<<<(NT * Dd) / 256, 256>>>(out);
}

// round 3
// speedup vs baseline: 1.8865x; 1.8865x over previous
#include <cuda_runtime.h>

#define Bb     2
#define Ss     1024
#define Dd     1024
#define Hh     16
#define HDh    64
#define NT     (Bb*Ss)
#define Ee     31
#define INTERi 1024
#define EPSf   1e-5f
#define SLOTS  (NT*3)

// ---------------- scratch ----------------
__device__ float g_xn  [NT*Dd];
__device__ float g_qb  [NT*Dd];
__device__ float g_kb  [NT*Dd];
__device__ float g_vb  [NT*Dd];
__device__ float g_ctx [NT*Dd];
__device__ float g_attn[NT*Dd];
__device__ float g_an  [NT*Dd];
__device__ float g_t1  [NT*INTERi];
__device__ float g_h   [SLOTS*INTERi];
__device__ float g_part[SLOTS*Dd];
__device__ int   g_topi[SLOTS];
__device__ float g_topv[SLOTS];
__device__ int   g_cnt[Ee];
__device__ int   g_off[Ee];
__device__ int   g_cur[Ee];
__device__ int   g_slot_tok [SLOTS];
__device__ int   g_slot_rank[SLOTS];
__device__ float g_slot_gate[SLOTS];

__device__ __forceinline__ float gelu_f(float v) {
    return 0.5f * v * (1.0f + erff(v * 0.70710678118654752f));
}

__global__ void reset_kernel() {
    int t = threadIdx.x;
    if (t < Ee) { g_cnt[t] = 0; g_cur[t] = 0; }
}

// ---------------- RMSNorm ----------------
__global__ void rmsnorm_kernel(const float* __restrict__ in,
                               const float* __restrict__ gamma,
                               float* __restrict__ out) {
    int row = blockIdx.x;
    const float* p = in + row * Dd;
    float ss = 0.f;
    for (int d = threadIdx.x; d < Dd; d += blockDim.x) { float v = p[d]; ss += v * v; }
    for (int o = 16; o; o >>= 1) ss += __shfl_xor_sync(0xffffffffu, ss, o);
    __shared__ float red[8];
    int w = threadIdx.x >> 5;
    if ((threadIdx.x & 31) == 0) red[w] = ss;
    __syncthreads();
    if (threadIdx.x < 8) {
        float v = red[threadIdx.x];
        for (int o = 4; o; o >>= 1) v += __shfl_xor_sync(0xffu, v, o);
        if (threadIdx.x == 0) red[0] = v;
    }
    __syncthreads();
    float rinv = rsqrtf(red[0] * (1.0f / Dd) + EPSf);
    for (int d = threadIdx.x; d < Dd; d += blockDim.x)
        out[row * Dd + d] = p[d] * rinv * gamma[d];
}

// =====================================================================
// 128x128x16 GEMM core, 256 threads, 8x8 micro-tile, reg prefetch.
// Macros shared by all GEMM variants.
// =====================================================================
#define GEMM_DECLS                                                     \
    __shared__ __align__(16) float As[16][128];                        \
    __shared__ __align__(16) float Bs[16][128];                        \
    int tid = threadIdx.x;                                             \
    int tx = tid & 15, ty = tid >> 4;                                  \
    int arow = tid >> 2;                                               \
    int akq  = (tid & 3) * 4;                                          \
    int bk   = tid >> 5;                                               \
    int bn   = (tid & 31) * 4;                                         \
    float acc[8][8] = {};                                              \
    float4 a0, a1, b0, b1;

#define GEMM_STORE_SMEM                                                \
    As[akq+0][arow]     = a0.x; As[akq+1][arow]     = a0.y;            \
    As[akq+2][arow]     = a0.z; As[akq+3][arow]     = a0.w;            \
    As[akq+0][arow+64]  = a1.x; As[akq+1][arow+64]  = a1.y;            \
    As[akq+2][arow+64]  = a1.z; As[akq+3][arow+64]  = a1.w;            \
    *(float4*)&Bs[bk][bn]   = b0;                                      \
    *(float4*)&Bs[bk+8][bn] = b1;

#define GEMM_COMPUTE                                                   \
    _Pragma("unroll")                                                  \
    for (int kk = 0; kk < 16; kk++) {                                  \
        float4 x0 = *(const float4*)&As[kk][ty*8];                     \
        float4 x1 = *(const float4*)&As[kk][ty*8+4];                   \
        float4 y0 = *(const float4*)&Bs[kk][tx*8];                     \
        float4 y1 = *(const float4*)&Bs[kk][tx*8+4];                   \
        float av[8] = {x0.x,x0.y,x0.z,x0.w,x1.x,x1.y,x1.z,x1.w};       \
        float bv[8] = {y0.x,y0.y,y0.z,y0.w,y1.x,y1.y,y1.z,y1.w};       \
        _Pragma("unroll")                                              \
        for (int i = 0; i < 8; i++)                                    \
            _Pragma("unroll")                                          \
            for (int j = 0; j < 8; j++) acc[i][j] += av[i] * bv[j];    \
    }

// ---------------- generic GEMM: modes 0 plain, 1 gelu, 2 +res1(+res2) ----
__global__ __launch_bounds__(256) void gemm128_kernel(
    const float* __restrict__ A, const float* __restrict__ Bm,
    const float* __restrict__ bias, float* __restrict__ C,
    int N, int K, int mode,
    const float* __restrict__ res1, const float* __restrict__ res2)
{
    GEMM_DECLS
    int mb = blockIdx.y * 128, nb = blockIdx.x * 128;
    const float4* Ap0 = (const float4*)(A + (mb + arow) * K + akq);
    const float4* Ap1 = (const float4*)(A + (mb + arow + 64) * K + akq);
    const float4* Bp0 = (const float4*)(Bm + bk * N + nb + bn);
    const float4* Bp1 = (const float4*)(Bm + (bk + 8) * N + nb + bn);
    int strideB = 4 * N;  // float4 units per 16-k advance
    a0 = Ap0[0]; a1 = Ap1[0]; b0 = Bp0[0]; b1 = Bp1[0];
    int nt = K >> 4;
    for (int t = 0;; t++) {
        GEMM_STORE_SMEM
        __syncthreads();
        if (t + 1 < nt) {
            a0 = Ap0[(t+1)*4]; a1 = Ap1[(t+1)*4];
            b0 = Bp0[(size_t)(t+1)*strideB]; b1 = Bp1[(size_t)(t+1)*strideB];
        }
        GEMM_COMPUTE
        if (t + 1 == nt) break;
        __syncthreads();
    }
#pragma unroll
    for (int i = 0; i < 8; i++) {
        int m = mb + ty * 8 + i;
#pragma unroll
        for (int jj = 0; jj < 2; jj++) {
            int n = nb + tx * 8 + jj * 4;
            float4 v;
            v.x = acc[i][jj*4+0] + bias[n+0];
            v.y = acc[i][jj*4+1] + bias[n+1];
            v.z = acc[i][jj*4+2] + bias[n+2];
            v.w = acc[i][jj*4+3] + bias[n+3];
            if (mode == 1) {
                v.x = gelu_f(v.x); v.y = gelu_f(v.y);
                v.z = gelu_f(v.z); v.w = gelu_f(v.w);
            } else if (mode == 2) {
                float4 r = *(const float4*)&res1[m*N+n];
                v.x += r.x; v.y += r.y; v.z += r.z; v.w += r.w;
                if (res2) {
                    float4 r2 = *(const float4*)&res2[m*N+n];
                    v.x += r2.x; v.y += r2.y; v.z += r2.z; v.w += r2.w;
                }
            }
            *(float4*)&C[m*N+n] = v;
        }
    }
}

// ---------------- fused QKV GEMM, scatter to [B,H,S,HD] ----------------
__global__ __launch_bounds__(256) void qkv_kernel(
    const float* __restrict__ A,
    const float* __restrict__ qw, const float* __restrict__ qbias,
    const float* __restrict__ kw, const float* __restrict__ kbias,
    const float* __restrict__ vw, const float* __restrict__ vbias,
    float* __restrict__ qo, float* __restrict__ ko, float* __restrict__ vo)
{
    const float* Bm; const float* bias; float* C;
    if (blockIdx.z == 0)      { Bm = qw; bias = qbias; C = qo; }
    else if (blockIdx.z == 1) { Bm = kw; bias = kbias; C = ko; }
    else                      { Bm = vw; bias = vbias; C = vo; }
    const int N = Dd, K = Dd;
    GEMM_DECLS
    int mb = blockIdx.y * 128, nb = blockIdx.x * 128;
    const float4* Ap0 = (const float4*)(A + (mb + arow) * K + akq);
    const float4* Ap1 = (const float4*)(A + (mb + arow + 64) * K + akq);
    const float4* Bp0 = (const float4*)(Bm + bk * N + nb + bn);
    const float4* Bp1 = (const float4*)(Bm + (bk + 8) * N + nb + bn);
    a0 = Ap0[0]; a1 = Ap1[0]; b0 = Bp0[0]; b1 = Bp1[0];
    int nt = K >> 4;
    for (int t = 0;; t++) {
        GEMM_STORE_SMEM
        __syncthreads();
        if (t + 1 < nt) {
            a0 = Ap0[(t+1)*4]; a1 = Ap1[(t+1)*4];
            b0 = Bp0[(t+1)*4*N]; b1 = Bp1[(t+1)*4*N];
        }
        GEMM_COMPUTE
        if (t + 1 == nt) break;
        __syncthreads();
    }
#pragma unroll
    for (int i = 0; i < 8; i++) {
        int m = mb + ty * 8 + i;
        int b = m >> 10, s = m & 1023;
#pragma unroll
        for (int jj = 0; jj < 2; jj++) {
            int n = nb + tx * 8 + jj * 4;
            int h = n >> 6, hd = n & 63;
            float4 v;
            v.x = acc[i][jj*4+0] + bias[n+0];
            v.y = acc[i][jj*4+1] + bias[n+1];
            v.z = acc[i][jj*4+2] + bias[n+2];
            v.w = acc[i][jj*4+3] + bias[n+3];
            *(float4*)&C[(((b * Hh + h) * Ss + s) << 6) + hd] = v;
        }
    }
}

// ---------------- RoPE ----------------
__global__ void rope_kernel(float* __restrict__ p, const float* __restrict__ theta) {
    int v = blockIdx.x;
    int s = v & (Ss - 1);
    float* base = p + v * HDh;
    int i = threadIdx.x;
    float x1 = base[2 * i], x2 = base[2 * i + 1];
    float ang = (float)s * theta[i];
    float c = cosf(ang), sn = sinf(ang);
    __syncwarp();
    base[i]      = x1 * c - x2 * sn;
    base[32 + i] = x1 * sn + x2 * c;
}

// ---------------- causal flash attention (heavy tiles first) ----------------
__global__ void attn_kernel(const float* __restrict__ Q, const float* __restrict__ Kt,
                            const float* __restrict__ V, float* __restrict__ ctx) {
    int bh = blockIdx.y;
    int b = bh / Hh, h = bh % Hh;
    int qbase = (gridDim.x - 1 - blockIdx.x) * 128;   // heavy blocks first
    int t = threadIdx.x;
    int q = qbase + t;
    const float4* qrow = (const float4*)(Q + (bh * Ss + q) * HDh);
    float4 qr[16];
#pragma unroll
    for (int i = 0; i < 16; i++) qr[i] = qrow[i];
    float4 o[16];
#pragma unroll
    for (int i = 0; i < 16; i++) o[i] = make_float4(0.f, 0.f, 0.f, 0.f);
    float m = -1e30f, l = 0.f;
    __shared__ __align__(16) float4 ks[1024];
    __shared__ __align__(16) float4 vs[1024];
    int ntiles = qbase / 64 + 2;
    const float scale = 0.125f;
    for (int tile = 0; tile < ntiles; tile++) {
        int kb = tile * 64;
        const float4* kp = (const float4*)(Kt + (bh * Ss + kb) * HDh);
        const float4* vp = (const float4*)(V  + (bh * Ss + kb) * HDh);
        __syncthreads();
        for (int i = t; i < 1024; i += 128) { ks[i] = kp[i]; vs[i] = vp[i]; }
        __syncthreads();
        int jmax = q - kb + 1;
        if (jmax > 64) jmax = 64;
        for (int j = 0; j < jmax; j++) {
            float s_ = 0.f;
#pragma unroll
            for (int i = 0; i < 16; i++) {
                float4 kv = ks[j * 16 + i];
                s_ += qr[i].x * kv.x + qr[i].y * kv.y + qr[i].z * kv.z + qr[i].w * kv.w;
            }
            s_ *= scale;
            if (s_ <= m) {
                float p = __expf(s_ - m);
                l += p;
#pragma unroll
                for (int i = 0; i < 16; i++) {
                    float4 vv = vs[j * 16 + i];
                    o[i].x += p * vv.x; o[i].y += p * vv.y;
                    o[i].z += p * vv.z; o[i].w += p * vv.w;
                }
            } else {
                float corr = __expf(m - s_);
                m = s_;
                l = l * corr + 1.f;
#pragma unroll
                for (int i = 0; i < 16; i++) {
                    float4 vv = vs[j * 16 + i];
                    o[i].x = o[i].x * corr + vv.x; o[i].y = o[i].y * corr + vv.y;
                    o[i].z = o[i].z * corr + vv.z; o[i].w = o[i].w * corr + vv.w;
                }
            }
        }
    }
    float rl = 1.f / l;
    float4* out = (float4*)(ctx + (b * Ss + q) * Dd + h * HDh);
#pragma unroll
    for (int i = 0; i < 16; i++)
        out[i] = make_float4(o[i].x * rl, o[i].y * rl, o[i].z * rl, o[i].w * rl);
}

// ---------------- router ----------------
__global__ void router_kernel(const float* __restrict__ an, const float* __restrict__ W,
                              const float* __restrict__ bias) {
    int tkn = blockIdx.x;
    __shared__ float xs[Dd];
    for (int d = threadIdx.x; d < Dd; d += 32) xs[d] = an[tkn * Dd + d];
    __syncwarp();
    int e = threadIdx.x;
    float logit = -1e30f;
    if (e < Ee) {
        float acc = bias[e];
        for (int d = 0; d < Dd; d++) acc += xs[d] * W[d * Ee + e];
        logit = acc;
    }
    float mx = logit;
    for (int o = 16; o; o >>= 1) mx = fmaxf(mx, __shfl_xor_sync(0xffffffffu, mx, o));
    float ex = (e < Ee) ? __expf(logit - mx) : 0.f;
    float sm = ex;
    for (int o = 16; o; o >>= 1) sm += __shfl_xor_sync(0xffffffffu, sm, o);
    float pw = ex / sm;
    for (int it = 0; it < 3; it++) {
        float bv = pw; int bi = e;
        for (int o = 16; o; o >>= 1) {
            float ov = __shfl_xor_sync(0xffffffffu, bv, o);
            int   oi = __shfl_xor_sync(0xffffffffu, bi, o);
            if (ov > bv || (ov == bv && oi < bi)) { bv = ov; bi = oi; }
        }
        if (threadIdx.x == 0) {
            g_topi[tkn * 3 + it] = bi;
            g_topv[tkn * 3 + it] = bv;
            atomicAdd(&g_cnt[bi], 1);
        }
        if (e == bi) pw = -1.f;
    }
}

__global__ void scan_kernel() {
    if (threadIdx.x == 0) {
        int s = 0;
        for (int e = 0; e < Ee; e++) { g_off[e] = s; s += g_cnt[e]; }
    }
}

__global__ void fill_kernel() {
    int i = blockIdx.x * 256 + threadIdx.x;
    if (i >= SLOTS) return;
    int tkn = i / 3, r = i - tkn * 3;
    int e = g_topi[i];
    int pos = atomicAdd(&g_cur[e], 1);
    int slot = g_off[e] + pos;
    g_slot_tok[slot] = tkn;
    g_slot_rank[slot] = r;
    g_slot_gate[slot] = g_topv[i];
}

// ---------------- expert GEMM 1: h = gelu(gather(an) @ W1[e] + b1[e]) ----
__global__ __launch_bounds__(256) void egemm1_kernel(
    const float* __restrict__ re_w1, const float* __restrict__ re_b1)
{
    int e = blockIdx.z;
    int cnt = g_cnt[e];
    int mb = blockIdx.y * 128;
    if (mb >= cnt) return;
    int off = g_off[e];
    const float* Bm = re_w1 + (size_t)e * (Dd * INTERi);
    const int N = INTERi, K = Dd;
    GEMM_DECLS
    __shared__ int rows[128];
    int nb = blockIdx.x * 128;
    if (tid < 128) {
        int r = mb + tid;
        rows[tid] = (r < cnt) ? g_slot_tok[off + r] : -1;
    }
    __syncthreads();
    int r0 = rows[arow], r1 = rows[arow + 64];
    const float4* Ap0 = (r0 >= 0) ? (const float4*)(g_an + r0 * Dd + akq) : nullptr;
    const float4* Ap1 = (r1 >= 0) ? (const float4*)(g_an + r1 * Dd + akq) : nullptr;
    const float4* Bp0 = (const float4*)(Bm + bk * N + nb + bn);
    const float4* Bp1 = (const float4*)(Bm + (bk + 8) * N + nb + bn);
    float4 z4 = make_float4(0.f, 0.f, 0.f, 0.f);
    a0 = Ap0 ? Ap0[0] : z4; a1 = Ap1 ? Ap1[0] : z4;
    b0 = Bp0[0]; b1 = Bp1[0];
    int nt = K >> 4;
    for (int t = 0;; t++) {
        GEMM_STORE_SMEM
        __syncthreads();
        if (t + 1 < nt) {
            a0 = Ap0 ? Ap0[(t+1)*4] : z4;
            a1 = Ap1 ? Ap1[(t+1)*4] : z4;
            b0 = Bp0[(t+1)*4*N]; b1 = Bp1[(t+1)*4*N];
        }
        GEMM_COMPUTE
        if (t + 1 == nt) break;
        __syncthreads();
    }
    const float* bias = re_b1 + e * INTERi;
#pragma unroll
    for (int i = 0; i < 8; i++) {
        int row = mb + ty * 8 + i;
        if (row >= cnt) continue;
#pragma unroll
        for (int jj = 0; jj < 2; jj++) {
            int n = nb + tx * 8 + jj * 4;
            float4 v;
            v.x = gelu_f(acc[i][jj*4+0] + bias[n+0]);
            v.y = gelu_f(acc[i][jj*4+1] + bias[n+1]);
            v.z = gelu_f(acc[i][jj*4+2] + bias[n+2]);
            v.w = gelu_f(acc[i][jj*4+3] + bias[n+3]);
            *(float4*)&g_h[(size_t)(off + row) * INTERi + n] = v;
        }
    }
}

// ---------------- expert GEMM 2 ----------------
__global__ __launch_bounds__(256) void egemm2_kernel(
    const float* __restrict__ re_w2, const float* __restrict__ re_b2)
{
    int e = blockIdx.z;
    int cnt = g_cnt[e];
    int mb = blockIdx.y * 128;
    if (mb >= cnt) return;
    int off = g_off[e];
    const float* Bm = re_w2 + (size_t)e * (INTERi * Dd);
    const int N = Dd, K = INTERi;
    GEMM_DECLS
    int nb = blockIdx.x * 128;
    int m0 = mb + arow, m1 = mb + arow + 64;
    const float4* Ap0 = (m0 < cnt) ? (const float4*)(g_h + (size_t)(off + m0) * K + akq) : nullptr;
    const float4* Ap1 = (m1 < cnt) ? (const float4*)(g_h + (size_t)(off + m1) * K + akq) : nullptr;
    const float4* Bp0 = (const float4*)(Bm + bk * N + nb + bn);
    const float4* Bp1 = (const float4*)(Bm + (bk + 8) * N + nb + bn);
    float4 z4 = make_float4(0.f, 0.f, 0.f, 0.f);
    a0 = Ap0 ? Ap0[0] : z4; a1 = Ap1 ? Ap1[0] : z4;
    b0 = Bp0[0]; b1 = Bp1[0];
    int nt = K >> 4;
    for (int t = 0;; t++) {
        GEMM_STORE_SMEM
        __syncthreads();
        if (t + 1 < nt) {
            a0 = Ap0 ? Ap0[(t+1)*4] : z4;
            a1 = Ap1 ? Ap1[(t+1)*4] : z4;
            b0 = Bp0[(t+1)*4*N]; b1 = Bp1[(t+1)*4*N];
        }
        GEMM_COMPUTE
        if (t + 1 == nt) break;
        __syncthreads();
    }
    const float* bias = re_b2 + e * Dd;
#pragma unroll
    for (int i = 0; i < 8; i++) {
        int row = mb + ty * 8 + i;
        if (row >= cnt) continue;
        int slot = off + row;
        int tok = g_slot_tok[slot];
        int rnk = g_slot_rank[slot];
        float gate = g_slot_gate[slot];
        float* outp = g_part + (size_t)(tok * 3 + rnk) * Dd;
#pragma unroll
        for (int jj = 0; jj < 2; jj++) {
            int n = nb + tx * 8 + jj * 4;
            float4 v;
            v.x = gate * (acc[i][jj*4+0] + bias[n+0]);
            v.y = gate * (acc[i][jj*4+1] + bias[n+1]);
            v.z = gate * (acc[i][jj*4+2] + bias[n+2]);
            v.w = gate * (acc[i][jj*4+3] + bias[n+3]);
            *(float4*)&outp[n] = v;
        }
    }
}

// ---------------- final: out += routed partials ----------------
__global__ void final_kernel(float* __restrict__ out) {
    int i = blockIdx.x * 256 + threadIdx.x;
    int t = i >> 10, n = i & 1023;
    float v = out[i];
    v += g_part[(size_t)(t * 3 + 0) * Dd + n];
    v += g_part[(size_t)(t * 3 + 1) * Dd + n];
    v += g_part[(size_t)(t * 3 + 2) * Dd + n];
    out[i] = v;
}

// ---------------- launch ----------------
extern "C" void kernel_launch(void* const* d_in, const int* in_sizes, int n_in,
                              void* d_out, int out_size) {
    const float* x      = (const float*)d_in[0];
    const float* theta  = (const float*)d_in[2];
    const float* gamma1 = (const float*)d_in[3];
    const float* gamma2 = (const float*)d_in[4];
    const float* q_w  = (const float*)d_in[5];  const float* q_b  = (const float*)d_in[6];
    const float* k_w  = (const float*)d_in[7];  const float* k_b  = (const float*)d_in[8];
    const float* v_w  = (const float*)d_in[9];  const float* v_b  = (const float*)d_in[10];
    const float* o_w  = (const float*)d_in[11]; const float* o_b  = (const float*)d_in[12];
    const float* r_w  = (const float*)d_in[13]; const float* r_b  = (const float*)d_in[14];
    const float* sw1  = (const float*)d_in[15]; const float* sb1  = (const float*)d_in[16];
    const float* sw2  = (const float*)d_in[17]; const float* sb2  = (const float*)d_in[18];
    const float* rw1  = (const float*)d_in[19]; const float* rb1  = (const float*)d_in[20];
    const float* rw2  = (const float*)d_in[21]; const float* rb2  = (const float*)d_in[22];
    float* out = (float*)d_out;

    float *xn, *qb, *kb, *vb, *ctx, *attn, *an, *t1;
    cudaGetSymbolAddress((void**)&xn,   g_xn);
    cudaGetSymbolAddress((void**)&qb,   g_qb);
    cudaGetSymbolAddress((void**)&kb,   g_kb);
    cudaGetSymbolAddress((void**)&vb,   g_vb);
    cudaGetSymbolAddress((void**)&ctx,  g_ctx);
    cudaGetSymbolAddress((void**)&attn, g_attn);
    cudaGetSymbolAddress((void**)&an,   g_an);
    cudaGetSymbolAddress((void**)&t1,   g_t1);

    dim3 thr(256);
    dim3 grid_d (Dd / 128,     NT / 128);        // 8 x 16
    dim3 grid_i (INTERi / 128, NT / 128);        // 8 x 16

    reset_kernel<<<1, 32>>>();
    rmsnorm_kernel<<<NT, 256>>>(x, gamma1, xn);

    qkv_kernel<<<dim3(Dd/128, NT/128, 3), thr>>>(xn, q_w, q_b, k_w, k_b, v_w, v_b, qb, kb, vb);

    rope_kernel<<<Bb * Hh * Ss, 32>>>(qb, theta);
    rope_kernel<<<Bb * Hh * Ss, 32>>>(kb, theta);

    attn_kernel<<<dim3(Ss / 128, Bb * Hh), 128>>>(qb, kb, vb, ctx);

    gemm128_kernel<<<grid_d, thr>>>(ctx, o_w, o_b, attn, Dd, Dd, 2, xn, nullptr);
    rmsnorm_kernel<<<NT, 256>>>(attn, gamma2, an);

    gemm128_kernel<<<grid_i, thr>>>(an, sw1, sb1, t1, INTERi, Dd, 1, nullptr, nullptr);
    gemm128_kernel<<<grid_d, thr>>>(t1, sw2, sb2, out, Dd, INTERi, 2, an, attn);

    router_kernel<<<NT, 32>>>(an, r_w, r_b);
    scan_kernel<<<1, 32>>>();
    fill_kernel<<<(SLOTS + 255) / 256, 256>>>();

    egemm1_kernel<<<dim3(INTERi / 128, NT / 128, Ee), thr>>>(rw1, rb1);
    egemm2_kernel<<<dim3(Dd / 128, NT / 128, Ee), thr>>>(rw2, rb2);

    final_kernel<<<(NT * Dd) / 256, 256>>>(out);
}